// round 14
// baseline (speedup 1.0000x reference)
#include <cuda_runtime.h>
#include <cuda_fp16.h>
#include <cstdint>

// ---------------- problem dims ----------------
constexpr int B_   = 32;
constexpr int CIN  = 256;
constexpr int COUT = 256;
constexpr int HW   = 1024;   // 32x32
constexpr int TDIM = 256;
constexpr int HID  = 64;
constexpr int E_   = 4;
constexpr int TAPS = 9;

// ---------------- device scratch (static: allocation rules) ----------------
__device__ __align__(16) __half g_xh[(size_t)B_ * HW * CIN];              // x fp16, PIXEL-major [b][px][cin]
__device__ float  g_ppart[B_ * CIN * 32];                                 // per-(b,cin,h) partial sums
__device__ float  g_rw[B_ * E_];
__device__ __align__(16) __half g_weff[(size_t)B_ * TAPS * COUT * CIN];   // [b][tap][cout][cin]
__device__ unsigned int g_bctr[B_];                                       // per-batch completion tickets

// ---------------- helpers ----------------
#define SW128(off)  ((off) ^ (((off) >> 3) & 0x70))   // 128B-row swizzle

__device__ __forceinline__ uint32_t smem_u32(const void* p) {
    uint32_t a;
    asm("{ .reg .u64 t; cvta.to.shared.u64 t, %1; cvt.u32.u64 %0, t; }"
        : "=r"(a) : "l"(p));
    return a;
}
__device__ __forceinline__ void ldsm_x4(uint32_t* r, uint32_t addr) {
    asm volatile("ldmatrix.sync.aligned.m8n8.x4.shared.b16 {%0,%1,%2,%3}, [%4];"
                 : "=r"(r[0]), "=r"(r[1]), "=r"(r[2]), "=r"(r[3]) : "r"(addr));
}
__device__ __forceinline__ void mma16816(float* c, const uint32_t* a,
                                         uint32_t b0, uint32_t b1) {
    asm volatile(
        "mma.sync.aligned.m16n8k16.row.col.f32.f16.f16.f32 "
        "{%0,%1,%2,%3}, {%4,%5,%6,%7}, {%8,%9}, {%0,%1,%2,%3};"
        : "+f"(c[0]), "+f"(c[1]), "+f"(c[2]), "+f"(c[3])
        : "r"(a[0]), "r"(a[1]), "r"(a[2]), "r"(a[3]), "r"(b0), "r"(b1));
}
__device__ __forceinline__ void cp_async16(uint32_t dst, const void* src) {
    asm volatile("cp.async.cg.shared.global [%0], [%1], 16;" :: "r"(dst), "l"(src));
}
#define CP_COMMIT() asm volatile("cp.async.commit_group;" ::: "memory")
#define CP_WAIT(N)  asm volatile("cp.async.wait_group %0;" :: "n"(N) : "memory")

// ---------------- kernel 1: transpose + pooled partials + INLINE last-block router ----------------
// block (h, b), 256 threads. XOR-swizzled smem transpose; row sums from smem.
// The 32nd-finishing block of each batch runs that batch's router MLP inline
// (threadFenceReduction pattern; counters never reset, (ticket&31)==31 test).
__global__ __launch_bounds__(256) void pool_convert_kernel(
    const float* __restrict__ x,
    const float* __restrict__ te,
    const float* __restrict__ Wq, const float* __restrict__ bq,
    const float* __restrict__ Wk, const float* __restrict__ bk,
    const float* __restrict__ Wv, const float* __restrict__ bv,
    const float* __restrict__ Wm1, const float* __restrict__ bm1,
    const float* __restrict__ Wm2, const float* __restrict__ bm2,
    const float* __restrict__ Wc, const float* __restrict__ bc) {
    const int hrow = blockIdx.x, b = blockIdx.y;
    const int tid = threadIdx.x, w = tid & 31, wrp = tid >> 5;
    __shared__ uint32_t sm[128 * 32];   // [cin-pair][w ^ cpair]

    #pragma unroll
    for (int it = 0; it < 16; it++) {
        int cpair = it * 8 + wrp;
        int cin0 = cpair * 2;
        float f0 = x[((size_t)(b * CIN + cin0) * HW) + hrow * 32 + w];
        float f1 = x[((size_t)(b * CIN + cin0 + 1) * HW) + hrow * 32 + w];
        __half2 hp = __floats2half2_rn(f0, f1);
        sm[cpair * 32 + (w ^ (cpair & 31))] = *reinterpret_cast<uint32_t*>(&hp);
    }
    __syncthreads();

    // phase 2: vectorized pixel-major writes
    const int w2 = tid >> 3, kq = tid & 7;
    __half* op = g_xh + ((size_t)(b * HW) + hrow * 32 + w2) * CIN;
    #pragma unroll
    for (int it = 0; it < 4; it++) {
        int ch = it * 8 + kq;            // 16B chunk (8 cins = 4 cpairs)
        uint4 v;
        v.x = sm[(ch * 4 + 0) * 32 + (w2 ^ ((ch * 4 + 0) & 31))];
        v.y = sm[(ch * 4 + 1) * 32 + (w2 ^ ((ch * 4 + 1) & 31))];
        v.z = sm[(ch * 4 + 2) * 32 + (w2 ^ ((ch * 4 + 2) & 31))];
        v.w = sm[(ch * 4 + 3) * 32 + (w2 ^ ((ch * 4 + 3) & 31))];
        *reinterpret_cast<uint4*>(op + ch * 8) = v;
    }

    // phase 3: row sums from smem (threads 0..127, one cpair each; conflict-free)
    if (tid < 128) {
        const int cpair = tid;
        float s0 = 0.f, s1 = 0.f;
        #pragma unroll
        for (int ww = 0; ww < 32; ww++) {
            uint32_t u = sm[cpair * 32 + (ww ^ (cpair & 31))];
            __half2 hp = *reinterpret_cast<__half2*>(&u);
            float2 f = __half22float2(hp);
            s0 += f.x;
            s1 += f.y;
        }
        g_ppart[(b * CIN + cpair * 2) * 32 + hrow] = s0;
        g_ppart[(b * CIN + cpair * 2 + 1) * 32 + hrow] = s1;
    }

    // phase 4: last block of this batch runs the router MLP inline
    __threadfence();
    __syncthreads();
    __shared__ unsigned s_ticket;
    if (tid == 0) s_ticket = atomicAdd(&g_bctr[b], 1u);
    __syncthreads();
    if ((s_ticket & 31u) != 31u) return;

    __shared__ float s_in[TDIM], s_p[CIN], s_xa[HID], s_h[HID], s_xm[HID], s_l[E_];
    const int j = tid;
    if (j < TDIM) s_in[j] = te[b * TDIM + j];
    if (j < CIN) {
        const float* pp = g_ppart + (b * CIN + j) * 32;
        float s = 0.f;
        #pragma unroll
        for (int hh = 0; hh < 32; hh++) s += pp[hh];
        s_p[j] = s * (1.f / 1024.f);
    }
    __syncthreads();

    if (j < HID) {
        float q = bq[j], k = bk[j], v = bv[j];
        for (int i = 0; i < TDIM; i++) q += Wq[j * TDIM + i] * s_in[i];
        for (int i = 0; i < CIN; i++) {
            float p = s_p[i];
            k += Wk[j * CIN + i] * p;
            v += Wv[j * CIN + i] * p;
        }
        float attn = 1.f / (1.f + expf(-(q * k)));
        s_xa[j] = v * attn;
    }
    __syncthreads();

    if (j < HID) {
        float hh = bm1[j];
        for (int i = 0; i < HID; i++) hh += Wm1[j * HID + i] * s_xa[i];
        s_h[j] = hh / (1.f + expf(-hh));   // silu
    }
    __syncthreads();

    if (j < HID) {
        float xm = s_xa[j] + bm2[j];
        for (int i = 0; i < HID; i++) xm += Wm2[j * HID + i] * s_h[i];
        s_xm[j] = xm;
    }
    __syncthreads();

    if (j < E_) {
        float l = bc[j];
        for (int i = 0; i < HID; i++) l += Wc[j * HID + i] * s_xm[i];
        s_l[j] = l;
    }
    __syncthreads();
    if (j == 0) {
        float mx = s_l[0];
        for (int e = 1; e < E_; e++) mx = fmaxf(mx, s_l[e]);
        float smx = 0.f, ex[E_];
        for (int e = 0; e < E_; e++) { ex[e] = expf(s_l[e] - mx); smx += ex[e]; }
        float inv = 1.f / smx;
        for (int e = 0; e < E_; e++) g_rw[b * E_ + e] = ex[e] * inv;
    }
}

// ---------------- kernel 3: mix expert weights -> g_weff [b][tap][cout][cin] fp16 ----------------
// grid=COUT, 256 threads = (cin-pair 0..127, batch-half 0..1). Single 36 KB
// weight read per block; half2 coalesced stores; 16-batch serial depth.
__global__ __launch_bounds__(256) void mix_kernel(const float* __restrict__ weight) {
    const int o = blockIdx.x, tid = threadIdx.x;
    const int t2 = tid & 127;            // cin pair
    const int bh = tid >> 7;             // batch half
    __shared__ float ws[E_ * CIN * TAPS];   // 36 KB: weight[:, o, :, :]
    __shared__ float srw[B_ * E_];
    for (int e = 0; e < E_; e++) {
        const float* src = weight + (size_t)(e * COUT + o) * (CIN * TAPS);
        for (int i = tid; i < CIN * TAPS; i += 256) ws[e * CIN * TAPS + i] = src[i];
    }
    for (int i = tid; i < B_ * E_; i += 256) srw[i] = g_rw[i];
    __syncthreads();

    const int c0 = t2 * 2;
    float wv[E_][TAPS][2];
    #pragma unroll
    for (int e = 0; e < E_; e++)
        #pragma unroll
        for (int t = 0; t < TAPS; t++) {
            wv[e][t][0] = ws[e * CIN * TAPS + c0 * TAPS + t];
            wv[e][t][1] = ws[e * CIN * TAPS + (c0 + 1) * TAPS + t];
        }

    #pragma unroll 1
    for (int bi = 0; bi < 16; bi++) {
        const int b = bh * 16 + bi;
        float r0 = srw[b * 4 + 0], r1 = srw[b * 4 + 1];
        float r2 = srw[b * 4 + 2], r3 = srw[b * 4 + 3];
        #pragma unroll
        for (int t = 0; t < TAPS; t++) {
            float v0 = r0 * wv[0][t][0] + r1 * wv[1][t][0] + r2 * wv[2][t][0] + r3 * wv[3][t][0];
            float v1 = r0 * wv[0][t][1] + r1 * wv[1][t][1] + r2 * wv[2][t][1] + r3 * wv[3][t][1];
            __half2 hv = __floats2half2_rn(v0, v1);
            *reinterpret_cast<__half2*>(
                g_weff + (((size_t)b * TAPS + t) * COUT + o) * CIN + c0) = hv;
        }
    }
}

// ---------------- kernel 4: batched implicit-GEMM conv via mma.sync (HMMA) ----------------
// (unchanged best: 4 warps 64x64, triple-buffered A, async double-buffered sX)
constexpr int PIXB = 144;                 // bytes per pixel in sX (64 cin + 8 pad halves)
constexpr int ROWB = 34 * PIXB;           // 4896 B per image row (halo cols 0 and 33)
constexpr int SXB  = 6 * ROWB;            // 29376 per sX buffer
constexpr int SA_OFF = 59392;             // >= 2*SXB, 1024-aligned
constexpr int SA_BYTES = 128 * 128;       // 16 KB per A buffer
constexpr int CONV_SMEM = SA_OFF + 3 * SA_BYTES;   // 108544

__global__ __launch_bounds__(128, 2) void conv_kernel(float* __restrict__ out) {
    extern __shared__ char smem[];
    char* sx = smem;
    const uint32_t sxa = smem_u32(sx);
    const uint32_t saa[3] = { sxa + SA_OFF, sxa + SA_OFF + SA_BYTES,
                              sxa + SA_OFF + 2 * SA_BYTES };

    const int tid = threadIdx.x, lid = tid & 31, wid = tid >> 5;
    const int nt = blockIdx.x, mt = blockIdx.y, b = blockIdx.z;
    const int wm = wid & 1, wn = wid >> 1;
    const int h0 = nt * 4;

    const __half* __restrict__ xb2 = g_xh + (size_t)b * HW * CIN;   // pixel-major
    const __half* __restrict__ wbase =
        g_weff + ((size_t)b * TAPS * COUT + (size_t)mt * 128) * CIN;

    float acc[4][8][4];
    #pragma unroll
    for (int mi = 0; mi < 4; mi++)
        #pragma unroll
        for (int ni = 0; ni < 8; ni++)
            #pragma unroll
            for (int q = 0; q < 4; q++) acc[mi][ni][q] = 0.f;

    uint32_t bg[4];
    {
        int kh = (lid >> 3) & 1, nodd = lid >> 4, pr = lid & 7;
        #pragma unroll
        for (int g = 0; g < 4; g++) {
            int n = wn * 64 + (2 * g + nodd) * 8 + pr;
            int r = n >> 5, w = n & 31;
            bg[g] = sxa + (uint32_t)(((r + 1) * 34 + (w + 1)) * PIXB + kh * 16);
        }
    }

    auto prefetchA = [&](int tap, int cc, uint32_t dst) {
        const __half* asrc = wbase + (size_t)tap * COUT * CIN + cc * 64;
        #pragma unroll
        for (int i = 0; i < 8; i++) {
            int idx = i * 128 + tid;
            int m = idx >> 3, j = idx & 7;
            cp_async16(dst + SW128((uint32_t)(m * 128 + j * 16)), asrc + m * CIN + j * 8);
        }
    };

    auto fillXasync = [&](int cn) {
        const int w = tid >> 2, jj = tid & 3;
        const uint32_t dstb = sxa + (uint32_t)((cn & 1) * SXB + (1 + w) * PIXB + jj * 32);
        const char* srcb = (const char*)(xb2 + (size_t)cn * 64) + (size_t)w * (CIN * 2) + jj * 32;
        #pragma unroll
        for (int rr = 0; rr < 6; rr++) {
            int h = h0 + rr - 1;
            if ((unsigned)h < 32u) {
                const char* s = srcb + (size_t)h * (32 * CIN * 2);
                uint32_t d = dstb + rr * ROWB;
                cp_async16(d, s);
                cp_async16(d + 16, s + 16);
            }
        }
    };

    for (int i = tid; i < 216; i += 128) {       // halo cols: 2 buf x 6 rr x 2 col x 9 u4
        int u = i % 9, rem = i / 9;
        int col = rem & 1, rr = (rem >> 1) % 6, bf = rem / 12;
        *reinterpret_cast<uint4*>(sx + bf * SXB + rr * ROWB + (col ? 33 : 0) * PIXB + u * 16) =
            make_uint4(0u, 0u, 0u, 0u);
    }
    if (nt == 0 || nt == 7) {                    // one out-of-range image row per CTA
        int RR = (nt == 0) ? 0 : 5;
        for (int i = tid; i < 612; i += 128) {   // 2 buf x 306 u4
            int bf = i / 306, u = i % 306;
            *reinterpret_cast<uint4*>(sx + bf * SXB + RR * ROWB + u * 16) =
                make_uint4(0u, 0u, 0u, 0u);
        }
    }
    fillXasync(0);
    prefetchA(0, 0, saa[0]);
    CP_COMMIT();                                  // group: sX(0) + A(0)
    prefetchA(1, 0, saa[1]);
    CP_COMMIT();                                  // group: A(1)

    #pragma unroll 1
    for (int cc = 0; cc < 4; cc++) {
        const uint32_t xoff = (uint32_t)((cc & 1) * SXB);
        #pragma unroll
        for (int tap = 0; tap < TAPS; tap++) {
            const bool lastS = (cc == 3) && (tap == 8);
            if (lastS) { CP_WAIT(0); } else { CP_WAIT(1); }   // A(s) [+sX(cc)] resident
            __syncthreads();

            if (!((cc == 3) && (tap >= 7))) {
                const int ntap = (tap + 2 < TAPS) ? tap + 2 : tap + 2 - TAPS;
                const int ncc  = (tap + 2 < TAPS) ? cc : cc + 1;
                prefetchA(ntap, ncc, saa[(tap + 2) % 3]);
                if (tap == 0 && cc < 3) fillXasync(cc + 1);    // next chunk's sX, async
                CP_COMMIT();
            }

            const uint32_t sa = saa[tap % 3];
            const int dh = tap / 3 - 1, dw = tap % 3 - 1;
            const int delta = (dh * 34 + dw) * PIXB;

            #pragma unroll
            for (int ks = 0; ks < 4; ks++) {
                uint32_t afr[4][4];
                #pragma unroll
                for (int mi = 0; mi < 4; mi++) {
                    int row = wm * 64 + mi * 16 + (lid & 15);
                    uint32_t off = (uint32_t)(row * 128 + ks * 32 + (lid >> 4) * 16);
                    ldsm_x4(afr[mi], sa + SW128(off));
                }
                uint32_t breg[4][4];
                const uint32_t dlt = xoff + (uint32_t)(delta + ks * 32);
                #pragma unroll
                for (int g = 0; g < 4; g++) ldsm_x4(breg[g], bg[g] + dlt);
                #pragma unroll
                for (int mi = 0; mi < 4; mi++)
                    #pragma unroll
                    for (int nb = 0; nb < 8; nb++) {
                        uint32_t b0 = breg[nb >> 1][(nb & 1) * 2];
                        uint32_t b1 = breg[nb >> 1][(nb & 1) * 2 + 1];
                        mma16816(acc[mi][nb], afr[mi], b0, b1);
                    }
            }
        }
    }

    // ---- epilogue: accum regs -> out ----
    #pragma unroll
    for (int mi = 0; mi < 4; mi++) {
        #pragma unroll
        for (int ni = 0; ni < 8; ni++) {
            int row = mt * 128 + wm * 64 + mi * 16 + (lid >> 2);
            int col = nt * 128 + wn * 64 + ni * 8 + (lid & 3) * 2;
            float* op0 = out + ((size_t)b * COUT + row) * HW + col;
            float* op1 = op0 + 8 * HW;   // row + 8
            *reinterpret_cast<float2*>(op0) = make_float2(acc[mi][ni][0], acc[mi][ni][1]);
            *reinterpret_cast<float2*>(op1) = make_float2(acc[mi][ni][2], acc[mi][ni][3]);
        }
    }
}

// ---------------- launcher ----------------
extern "C" void kernel_launch(void* const* d_in, const int* in_sizes, int n_in,
                              void* d_out, int out_size) {
    const float* x      = (const float*)d_in[0];
    const float* te     = (const float*)d_in[1];
    const float* weight = (const float*)d_in[2];
    const float* Wq = (const float*)d_in[3],  *bq = (const float*)d_in[4];
    const float* Wk = (const float*)d_in[5],  *bk = (const float*)d_in[6];
    const float* Wv = (const float*)d_in[7],  *bv = (const float*)d_in[8];
    const float* Wm1 = (const float*)d_in[9],  *bm1 = (const float*)d_in[10];
    const float* Wm2 = (const float*)d_in[11], *bm2 = (const float*)d_in[12];
    const float* Wc  = (const float*)d_in[13], *bc  = (const float*)d_in[14];
    float* out = (float*)d_out;

    cudaFuncSetAttribute(conv_kernel, cudaFuncAttributeMaxDynamicSharedMemorySize,
                         CONV_SMEM);

    pool_convert_kernel<<<dim3(32, B_), 256>>>(x, te, Wq, bq, Wk, bk, Wv, bv,
                                               Wm1, bm1, Wm2, bm2, Wc, bc);
    mix_kernel<<<COUT, 256>>>(weight);
    conv_kernel<<<dim3(8, 2, B_), 128, CONV_SMEM>>>(out);
}

// round 15
// speedup vs baseline: 1.0042x; 1.0042x over previous
#include <cuda_runtime.h>
#include <cuda_fp16.h>
#include <cstdint>

// ---------------- problem dims ----------------
constexpr int B_   = 32;
constexpr int CIN  = 256;
constexpr int COUT = 256;
constexpr int HW   = 1024;   // 32x32
constexpr int TDIM = 256;
constexpr int HID  = 64;
constexpr int E_   = 4;
constexpr int TAPS = 9;

// ---------------- device scratch (static: allocation rules) ----------------
__device__ __align__(16) __half g_xh[(size_t)B_ * HW * CIN];              // x fp16, PIXEL-major [b][px][cin]
__device__ float  g_ppart[B_ * CIN * 32];                                 // per-(b,cin,h) partial sums
__device__ float  g_rw[B_ * E_];
__device__ __align__(16) __half g_weff[(size_t)B_ * TAPS * COUT * CIN];   // [b][tap][cout][cin]
__device__ unsigned int g_bctr[B_];                                       // per-batch completion tickets

// ---------------- helpers ----------------
#define SW128(off)  ((off) ^ (((off) >> 3) & 0x70))   // 128B-row swizzle

__device__ __forceinline__ uint32_t smem_u32(const void* p) {
    uint32_t a;
    asm("{ .reg .u64 t; cvta.to.shared.u64 t, %1; cvt.u32.u64 %0, t; }"
        : "=r"(a) : "l"(p));
    return a;
}
__device__ __forceinline__ void ldsm_x4(uint32_t* r, uint32_t addr) {
    asm volatile("ldmatrix.sync.aligned.m8n8.x4.shared.b16 {%0,%1,%2,%3}, [%4];"
                 : "=r"(r[0]), "=r"(r[1]), "=r"(r[2]), "=r"(r[3]) : "r"(addr));
}
__device__ __forceinline__ void mma16816(float* c, const uint32_t* a,
                                         uint32_t b0, uint32_t b1) {
    asm volatile(
        "mma.sync.aligned.m16n8k16.row.col.f32.f16.f16.f32 "
        "{%0,%1,%2,%3}, {%4,%5,%6,%7}, {%8,%9}, {%0,%1,%2,%3};"
        : "+f"(c[0]), "+f"(c[1]), "+f"(c[2]), "+f"(c[3])
        : "r"(a[0]), "r"(a[1]), "r"(a[2]), "r"(a[3]), "r"(b0), "r"(b1));
}
__device__ __forceinline__ void cp_async16(uint32_t dst, const void* src) {
    asm volatile("cp.async.cg.shared.global [%0], [%1], 16;" :: "r"(dst), "l"(src));
}
#define CP_COMMIT() asm volatile("cp.async.commit_group;" ::: "memory")
#define CP_WAIT(N)  asm volatile("cp.async.wait_group %0;" :: "n"(N) : "memory")

// scoped release+acquire ticket (NO per-thread membar storm)
__device__ __forceinline__ unsigned ticket_acq_rel(unsigned* ctr) {
    unsigned old;
    asm volatile("atom.acq_rel.gpu.global.add.u32 %0, [%1], 1;"
                 : "=r"(old) : "l"(ctr) : "memory");
    return old;
}

// ---------------- kernel 1: transpose + pooled partials + INLINE last-block router ----------------
// block (h, b), 256 threads. XOR-swizzled smem transpose; row sums from smem.
// The 32nd-arriving block of each batch runs that batch's router MLP inline.
// Publication: __syncthreads() + ONE acq_rel scoped atomic per block.
__global__ __launch_bounds__(256) void pool_convert_kernel(
    const float* __restrict__ x,
    const float* __restrict__ te,
    const float* __restrict__ Wq, const float* __restrict__ bq,
    const float* __restrict__ Wk, const float* __restrict__ bk,
    const float* __restrict__ Wv, const float* __restrict__ bv,
    const float* __restrict__ Wm1, const float* __restrict__ bm1,
    const float* __restrict__ Wm2, const float* __restrict__ bm2,
    const float* __restrict__ Wc, const float* __restrict__ bc) {
    const int hrow = blockIdx.x, b = blockIdx.y;
    const int tid = threadIdx.x, w = tid & 31, wrp = tid >> 5;
    __shared__ uint32_t sm[128 * 32];   // [cin-pair][w ^ cpair]

    #pragma unroll
    for (int it = 0; it < 16; it++) {
        int cpair = it * 8 + wrp;
        int cin0 = cpair * 2;
        float f0 = x[((size_t)(b * CIN + cin0) * HW) + hrow * 32 + w];
        float f1 = x[((size_t)(b * CIN + cin0 + 1) * HW) + hrow * 32 + w];
        __half2 hp = __floats2half2_rn(f0, f1);
        sm[cpair * 32 + (w ^ (cpair & 31))] = *reinterpret_cast<uint32_t*>(&hp);
    }
    __syncthreads();

    // phase 2: vectorized pixel-major writes
    const int w2 = tid >> 3, kq = tid & 7;
    __half* op = g_xh + ((size_t)(b * HW) + hrow * 32 + w2) * CIN;
    #pragma unroll
    for (int it = 0; it < 4; it++) {
        int ch = it * 8 + kq;            // 16B chunk (8 cins = 4 cpairs)
        uint4 v;
        v.x = sm[(ch * 4 + 0) * 32 + (w2 ^ ((ch * 4 + 0) & 31))];
        v.y = sm[(ch * 4 + 1) * 32 + (w2 ^ ((ch * 4 + 1) & 31))];
        v.z = sm[(ch * 4 + 2) * 32 + (w2 ^ ((ch * 4 + 2) & 31))];
        v.w = sm[(ch * 4 + 3) * 32 + (w2 ^ ((ch * 4 + 3) & 31))];
        *reinterpret_cast<uint4*>(op + ch * 8) = v;
    }

    // phase 3: row sums from smem (threads 0..127, one cpair each; conflict-free)
    if (tid < 128) {
        const int cpair = tid;
        float s0 = 0.f, s1 = 0.f;
        #pragma unroll
        for (int ww = 0; ww < 32; ww++) {
            uint32_t u = sm[cpair * 32 + (ww ^ (cpair & 31))];
            __half2 hp = *reinterpret_cast<__half2*>(&u);
            float2 f = __half22float2(hp);
            s0 += f.x;
            s1 += f.y;
        }
        g_ppart[(b * CIN + cpair * 2) * 32 + hrow] = s0;
        g_ppart[(b * CIN + cpair * 2 + 1) * 32 + hrow] = s1;
    }

    // phase 4: last-arriving block of this batch runs the router MLP inline
    __syncthreads();                       // all block writes ordered before ticket
    __shared__ unsigned s_ticket;
    if (tid == 0) s_ticket = ticket_acq_rel(&g_bctr[b]);   // release + acquire
    __syncthreads();
    if ((s_ticket & 31u) != 31u) return;

    __shared__ float s_in[TDIM], s_p[CIN], s_xa[HID], s_h[HID], s_xm[HID], s_l[E_];
    const int j = tid;
    if (j < TDIM) s_in[j] = te[b * TDIM + j];
    if (j < CIN) {
        const float* pp = g_ppart + (b * CIN + j) * 32;
        float s = 0.f;
        #pragma unroll
        for (int hh = 0; hh < 32; hh++) s += pp[hh];
        s_p[j] = s * (1.f / 1024.f);
    }
    __syncthreads();

    if (j < HID) {
        float q = bq[j], k = bk[j], v = bv[j];
        for (int i = 0; i < TDIM; i++) q += Wq[j * TDIM + i] * s_in[i];
        for (int i = 0; i < CIN; i++) {
            float p = s_p[i];
            k += Wk[j * CIN + i] * p;
            v += Wv[j * CIN + i] * p;
        }
        float attn = 1.f / (1.f + expf(-(q * k)));
        s_xa[j] = v * attn;
    }
    __syncthreads();

    if (j < HID) {
        float hh = bm1[j];
        for (int i = 0; i < HID; i++) hh += Wm1[j * HID + i] * s_xa[i];
        s_h[j] = hh / (1.f + expf(-hh));   // silu
    }
    __syncthreads();

    if (j < HID) {
        float xm = s_xa[j] + bm2[j];
        for (int i = 0; i < HID; i++) xm += Wm2[j * HID + i] * s_h[i];
        s_xm[j] = xm;
    }
    __syncthreads();

    if (j < E_) {
        float l = bc[j];
        for (int i = 0; i < HID; i++) l += Wc[j * HID + i] * s_xm[i];
        s_l[j] = l;
    }
    __syncthreads();
    if (j == 0) {
        float mx = s_l[0];
        for (int e = 1; e < E_; e++) mx = fmaxf(mx, s_l[e]);
        float smx = 0.f, ex[E_];
        for (int e = 0; e < E_; e++) { ex[e] = expf(s_l[e] - mx); smx += ex[e]; }
        float inv = 1.f / smx;
        for (int e = 0; e < E_; e++) g_rw[b * E_ + e] = ex[e] * inv;
    }
}

// ---------------- kernel 3: mix expert weights -> g_weff [b][tap][cout][cin] fp16 ----------------
// grid=COUT, 256 threads = (cin-pair 0..127, batch-half 0..1). Single 36 KB
// weight read per block; half2 coalesced stores; 16-batch serial depth.
__global__ __launch_bounds__(256) void mix_kernel(const float* __restrict__ weight) {
    const int o = blockIdx.x, tid = threadIdx.x;
    const int t2 = tid & 127;            // cin pair
    const int bh = tid >> 7;             // batch half
    __shared__ float ws[E_ * CIN * TAPS];   // 36 KB: weight[:, o, :, :]
    __shared__ float srw[B_ * E_];
    for (int e = 0; e < E_; e++) {
        const float* src = weight + (size_t)(e * COUT + o) * (CIN * TAPS);
        for (int i = tid; i < CIN * TAPS; i += 256) ws[e * CIN * TAPS + i] = src[i];
    }
    for (int i = tid; i < B_ * E_; i += 256) srw[i] = g_rw[i];
    __syncthreads();

    const int c0 = t2 * 2;
    float wv[E_][TAPS][2];
    #pragma unroll
    for (int e = 0; e < E_; e++)
        #pragma unroll
        for (int t = 0; t < TAPS; t++) {
            wv[e][t][0] = ws[e * CIN * TAPS + c0 * TAPS + t];
            wv[e][t][1] = ws[e * CIN * TAPS + (c0 + 1) * TAPS + t];
        }

    #pragma unroll 1
    for (int bi = 0; bi < 16; bi++) {
        const int b = bh * 16 + bi;
        float r0 = srw[b * 4 + 0], r1 = srw[b * 4 + 1];
        float r2 = srw[b * 4 + 2], r3 = srw[b * 4 + 3];
        #pragma unroll
        for (int t = 0; t < TAPS; t++) {
            float v0 = r0 * wv[0][t][0] + r1 * wv[1][t][0] + r2 * wv[2][t][0] + r3 * wv[3][t][0];
            float v1 = r0 * wv[0][t][1] + r1 * wv[1][t][1] + r2 * wv[2][t][1] + r3 * wv[3][t][1];
            __half2 hv = __floats2half2_rn(v0, v1);
            *reinterpret_cast<__half2*>(
                g_weff + (((size_t)b * TAPS + t) * COUT + o) * CIN + c0) = hv;
        }
    }
}

// ---------------- kernel 4: batched implicit-GEMM conv via mma.sync (HMMA) ----------------
// (unchanged best: 4 warps 64x64, triple-buffered A, async double-buffered sX)
constexpr int PIXB = 144;                 // bytes per pixel in sX (64 cin + 8 pad halves)
constexpr int ROWB = 34 * PIXB;           // 4896 B per image row (halo cols 0 and 33)
constexpr int SXB  = 6 * ROWB;            // 29376 per sX buffer
constexpr int SA_OFF = 59392;             // >= 2*SXB, 1024-aligned
constexpr int SA_BYTES = 128 * 128;       // 16 KB per A buffer
constexpr int CONV_SMEM = SA_OFF + 3 * SA_BYTES;   // 108544

__global__ __launch_bounds__(128, 2) void conv_kernel(float* __restrict__ out) {
    extern __shared__ char smem[];
    char* sx = smem;
    const uint32_t sxa = smem_u32(sx);
    const uint32_t saa[3] = { sxa + SA_OFF, sxa + SA_OFF + SA_BYTES,
                              sxa + SA_OFF + 2 * SA_BYTES };

    const int tid = threadIdx.x, lid = tid & 31, wid = tid >> 5;
    const int nt = blockIdx.x, mt = blockIdx.y, b = blockIdx.z;
    const int wm = wid & 1, wn = wid >> 1;
    const int h0 = nt * 4;

    const __half* __restrict__ xb2 = g_xh + (size_t)b * HW * CIN;   // pixel-major
    const __half* __restrict__ wbase =
        g_weff + ((size_t)b * TAPS * COUT + (size_t)mt * 128) * CIN;

    float acc[4][8][4];
    #pragma unroll
    for (int mi = 0; mi < 4; mi++)
        #pragma unroll
        for (int ni = 0; ni < 8; ni++)
            #pragma unroll
            for (int q = 0; q < 4; q++) acc[mi][ni][q] = 0.f;

    uint32_t bg[4];
    {
        int kh = (lid >> 3) & 1, nodd = lid >> 4, pr = lid & 7;
        #pragma unroll
        for (int g = 0; g < 4; g++) {
            int n = wn * 64 + (2 * g + nodd) * 8 + pr;
            int r = n >> 5, w = n & 31;
            bg[g] = sxa + (uint32_t)(((r + 1) * 34 + (w + 1)) * PIXB + kh * 16);
        }
    }

    auto prefetchA = [&](int tap, int cc, uint32_t dst) {
        const __half* asrc = wbase + (size_t)tap * COUT * CIN + cc * 64;
        #pragma unroll
        for (int i = 0; i < 8; i++) {
            int idx = i * 128 + tid;
            int m = idx >> 3, j = idx & 7;
            cp_async16(dst + SW128((uint32_t)(m * 128 + j * 16)), asrc + m * CIN + j * 8);
        }
    };

    auto fillXasync = [&](int cn) {
        const int w = tid >> 2, jj = tid & 3;
        const uint32_t dstb = sxa + (uint32_t)((cn & 1) * SXB + (1 + w) * PIXB + jj * 32);
        const char* srcb = (const char*)(xb2 + (size_t)cn * 64) + (size_t)w * (CIN * 2) + jj * 32;
        #pragma unroll
        for (int rr = 0; rr < 6; rr++) {
            int h = h0 + rr - 1;
            if ((unsigned)h < 32u) {
                const char* s = srcb + (size_t)h * (32 * CIN * 2);
                uint32_t d = dstb + rr * ROWB;
                cp_async16(d, s);
                cp_async16(d + 16, s + 16);
            }
        }
    };

    for (int i = tid; i < 216; i += 128) {       // halo cols: 2 buf x 6 rr x 2 col x 9 u4
        int u = i % 9, rem = i / 9;
        int col = rem & 1, rr = (rem >> 1) % 6, bf = rem / 12;
        *reinterpret_cast<uint4*>(sx + bf * SXB + rr * ROWB + (col ? 33 : 0) * PIXB + u * 16) =
            make_uint4(0u, 0u, 0u, 0u);
    }
    if (nt == 0 || nt == 7) {                    // one out-of-range image row per CTA
        int RR = (nt == 0) ? 0 : 5;
        for (int i = tid; i < 612; i += 128) {   // 2 buf x 306 u4
            int bf = i / 306, u = i % 306;
            *reinterpret_cast<uint4*>(sx + bf * SXB + RR * ROWB + u * 16) =
                make_uint4(0u, 0u, 0u, 0u);
        }
    }
    fillXasync(0);
    prefetchA(0, 0, saa[0]);
    CP_COMMIT();                                  // group: sX(0) + A(0)
    prefetchA(1, 0, saa[1]);
    CP_COMMIT();                                  // group: A(1)

    #pragma unroll 1
    for (int cc = 0; cc < 4; cc++) {
        const uint32_t xoff = (uint32_t)((cc & 1) * SXB);
        #pragma unroll
        for (int tap = 0; tap < TAPS; tap++) {
            const bool lastS = (cc == 3) && (tap == 8);
            if (lastS) { CP_WAIT(0); } else { CP_WAIT(1); }   // A(s) [+sX(cc)] resident
            __syncthreads();

            if (!((cc == 3) && (tap >= 7))) {
                const int ntap = (tap + 2 < TAPS) ? tap + 2 : tap + 2 - TAPS;
                const int ncc  = (tap + 2 < TAPS) ? cc : cc + 1;
                prefetchA(ntap, ncc, saa[(tap + 2) % 3]);
                if (tap == 0 && cc < 3) fillXasync(cc + 1);    // next chunk's sX, async
                CP_COMMIT();
            }

            const uint32_t sa = saa[tap % 3];
            const int dh = tap / 3 - 1, dw = tap % 3 - 1;
            const int delta = (dh * 34 + dw) * PIXB;

            #pragma unroll
            for (int ks = 0; ks < 4; ks++) {
                uint32_t afr[4][4];
                #pragma unroll
                for (int mi = 0; mi < 4; mi++) {
                    int row = wm * 64 + mi * 16 + (lid & 15);
                    uint32_t off = (uint32_t)(row * 128 + ks * 32 + (lid >> 4) * 16);
                    ldsm_x4(afr[mi], sa + SW128(off));
                }
                uint32_t breg[4][4];
                const uint32_t dlt = xoff + (uint32_t)(delta + ks * 32);
                #pragma unroll
                for (int g = 0; g < 4; g++) ldsm_x4(breg[g], bg[g] + dlt);
                #pragma unroll
                for (int mi = 0; mi < 4; mi++)
                    #pragma unroll
                    for (int nb = 0; nb < 8; nb++) {
                        uint32_t b0 = breg[nb >> 1][(nb & 1) * 2];
                        uint32_t b1 = breg[nb >> 1][(nb & 1) * 2 + 1];
                        mma16816(acc[mi][nb], afr[mi], b0, b1);
                    }
            }
        }
    }

    // ---- epilogue: accum regs -> out ----
    #pragma unroll
    for (int mi = 0; mi < 4; mi++) {
        #pragma unroll
        for (int ni = 0; ni < 8; ni++) {
            int row = mt * 128 + wm * 64 + mi * 16 + (lid >> 2);
            int col = nt * 128 + wn * 64 + ni * 8 + (lid & 3) * 2;
            float* op0 = out + ((size_t)b * COUT + row) * HW + col;
            float* op1 = op0 + 8 * HW;   // row + 8
            *reinterpret_cast<float2*>(op0) = make_float2(acc[mi][ni][0], acc[mi][ni][1]);
            *reinterpret_cast<float2*>(op1) = make_float2(acc[mi][ni][2], acc[mi][ni][3]);
        }
    }
}

// ---------------- launcher ----------------
extern "C" void kernel_launch(void* const* d_in, const int* in_sizes, int n_in,
                              void* d_out, int out_size) {
    const float* x      = (const float*)d_in[0];
    const float* te     = (const float*)d_in[1];
    const float* weight = (const float*)d_in[2];
    const float* Wq = (const float*)d_in[3],  *bq = (const float*)d_in[4];
    const float* Wk = (const float*)d_in[5],  *bk = (const float*)d_in[6];
    const float* Wv = (const float*)d_in[7],  *bv = (const float*)d_in[8];
    const float* Wm1 = (const float*)d_in[9],  *bm1 = (const float*)d_in[10];
    const float* Wm2 = (const float*)d_in[11], *bm2 = (const float*)d_in[12];
    const float* Wc  = (const float*)d_in[13], *bc  = (const float*)d_in[14];
    float* out = (float*)d_out;

    cudaFuncSetAttribute(conv_kernel, cudaFuncAttributeMaxDynamicSharedMemorySize,
                         CONV_SMEM);

    pool_convert_kernel<<<dim3(32, B_), 256>>>(x, te, Wq, bq, Wk, bk, Wv, bv,
                                               Wm1, bm1, Wm2, bm2, Wc, bc);
    mix_kernel<<<COUT, 256>>>(weight);
    conv_kernel<<<dim3(8, 2, B_), 128, CONV_SMEM>>>(out);
}

// round 16
// speedup vs baseline: 1.7728x; 1.7655x over previous
#include <cuda_runtime.h>
#include <cuda_fp16.h>
#include <cstdint>

// ---------------- problem dims ----------------
constexpr int B_   = 32;
constexpr int CIN  = 256;
constexpr int COUT = 256;
constexpr int HW   = 1024;   // 32x32
constexpr int TDIM = 256;
constexpr int HID  = 64;
constexpr int E_   = 4;
constexpr int TAPS = 9;

// ---------------- device scratch (static: allocation rules) ----------------
__device__ __align__(16) __half g_xh[(size_t)B_ * HW * CIN];              // x fp16, PIXEL-major [b][px][cin]
__device__ float  g_ppart[B_ * CIN * 32];                                 // per-(b,cin,h) partial sums
__device__ float  g_rw[B_ * E_];
__device__ __align__(16) __half g_weff[(size_t)B_ * TAPS * COUT * CIN];   // [b][tap][cout][cin]

// ---------------- helpers ----------------
#define SW128(off)  ((off) ^ (((off) >> 3) & 0x70))   // 128B-row swizzle

__device__ __forceinline__ uint32_t smem_u32(const void* p) {
    uint32_t a;
    asm("{ .reg .u64 t; cvta.to.shared.u64 t, %1; cvt.u32.u64 %0, t; }"
        : "=r"(a) : "l"(p));
    return a;
}
__device__ __forceinline__ void ldsm_x4(uint32_t* r, uint32_t addr) {
    asm volatile("ldmatrix.sync.aligned.m8n8.x4.shared.b16 {%0,%1,%2,%3}, [%4];"
                 : "=r"(r[0]), "=r"(r[1]), "=r"(r[2]), "=r"(r[3]) : "r"(addr));
}
__device__ __forceinline__ void mma16816(float* c, const uint32_t* a,
                                         uint32_t b0, uint32_t b1) {
    asm volatile(
        "mma.sync.aligned.m16n8k16.row.col.f32.f16.f16.f32 "
        "{%0,%1,%2,%3}, {%4,%5,%6,%7}, {%8,%9}, {%0,%1,%2,%3};"
        : "+f"(c[0]), "+f"(c[1]), "+f"(c[2]), "+f"(c[3])
        : "r"(a[0]), "r"(a[1]), "r"(a[2]), "r"(a[3]), "r"(b0), "r"(b1));
}
__device__ __forceinline__ void cp_async16(uint32_t dst, const void* src) {
    asm volatile("cp.async.cg.shared.global [%0], [%1], 16;" :: "r"(dst), "l"(src));
}
#define CP_COMMIT() asm volatile("cp.async.commit_group;" ::: "memory")
#define CP_WAIT(N)  asm volatile("cp.async.wait_group %0;" :: "n"(N) : "memory")
__device__ __forceinline__ void stg_cs_f2(float* p, float a, float b) {
    asm volatile("st.global.cs.v2.f32 [%0], {%1, %2};" :: "l"(p), "f"(a), "f"(b) : "memory");
}

// ---------------- kernel 1: transpose to pixel-major fp16 + pooled partials ----------------
// block (h, b), 256 threads. XOR-swizzled smem transpose; row sums computed from
// the smem tile by threads 0..127 (NO shfl reductions).
__global__ __launch_bounds__(256) void pool_convert_kernel(const float* __restrict__ x) {
    const int h = blockIdx.x, b = blockIdx.y;
    const int tid = threadIdx.x, w = tid & 31, wrp = tid >> 5;
    __shared__ uint32_t sm[128 * 32];   // [cin-pair][w ^ cpair]

    #pragma unroll
    for (int it = 0; it < 16; it++) {
        int cpair = it * 8 + wrp;
        int cin0 = cpair * 2;
        float f0 = x[((size_t)(b * CIN + cin0) * HW) + h * 32 + w];
        float f1 = x[((size_t)(b * CIN + cin0 + 1) * HW) + h * 32 + w];
        __half2 hp = __floats2half2_rn(f0, f1);
        sm[cpair * 32 + (w ^ (cpair & 31))] = *reinterpret_cast<uint32_t*>(&hp);
    }
    __syncthreads();

    // phase 2: vectorized pixel-major writes
    const int w2 = tid >> 3, kq = tid & 7;
    __half* op = g_xh + ((size_t)(b * HW) + h * 32 + w2) * CIN;
    #pragma unroll
    for (int it = 0; it < 4; it++) {
        int ch = it * 8 + kq;            // 16B chunk (8 cins = 4 cpairs)
        uint4 v;
        v.x = sm[(ch * 4 + 0) * 32 + (w2 ^ ((ch * 4 + 0) & 31))];
        v.y = sm[(ch * 4 + 1) * 32 + (w2 ^ ((ch * 4 + 1) & 31))];
        v.z = sm[(ch * 4 + 2) * 32 + (w2 ^ ((ch * 4 + 2) & 31))];
        v.w = sm[(ch * 4 + 3) * 32 + (w2 ^ ((ch * 4 + 3) & 31))];
        *reinterpret_cast<uint4*>(op + ch * 8) = v;
    }

    // phase 3: row sums from smem (threads 0..127, one cpair each; conflict-free)
    if (tid < 128) {
        const int cpair = tid;
        float s0 = 0.f, s1 = 0.f;
        #pragma unroll
        for (int ww = 0; ww < 32; ww++) {
            uint32_t u = sm[cpair * 32 + (ww ^ (cpair & 31))];
            __half2 hp = *reinterpret_cast<__half2*>(&u);
            float2 f = __half22float2(hp);
            s0 += f.x;
            s1 += f.y;
        }
        g_ppart[(b * CIN + cpair * 2) * 32 + h] = s0;
        g_ppart[(b * CIN + cpair * 2 + 1) * 32 + h] = s1;
    }
}

// ---------------- kernel 2: router MLP + softmax -> g_rw ----------------
__global__ __launch_bounds__(HID) void router_kernel(
    const float* __restrict__ te,
    const float* __restrict__ Wq, const float* __restrict__ bq,
    const float* __restrict__ Wk, const float* __restrict__ bk,
    const float* __restrict__ Wv, const float* __restrict__ bv,
    const float* __restrict__ Wm1, const float* __restrict__ bm1,
    const float* __restrict__ Wm2, const float* __restrict__ bm2,
    const float* __restrict__ Wc, const float* __restrict__ bc) {
    int b = blockIdx.x, j = threadIdx.x;
    __shared__ float s_in[TDIM], s_p[CIN], s_xa[HID], s_h[HID], s_xm[HID], s_l[E_];
    for (int i = j; i < TDIM; i += HID) s_in[i] = te[b * TDIM + i];
    for (int i = j; i < CIN; i += HID) {
        const float* pp = g_ppart + (b * CIN + i) * 32;
        float s = 0.f;
        #pragma unroll
        for (int hh = 0; hh < 32; hh++) s += pp[hh];
        s_p[i] = s * (1.f / 1024.f);
    }
    __syncthreads();

    float q = bq[j], k = bk[j], v = bv[j];
    for (int i = 0; i < TDIM; i++) q += Wq[j * TDIM + i] * s_in[i];
    for (int i = 0; i < CIN; i++) {
        float p = s_p[i];
        k += Wk[j * CIN + i] * p;
        v += Wv[j * CIN + i] * p;
    }
    float attn = 1.f / (1.f + expf(-(q * k)));
    float xa = v * attn;
    s_xa[j] = xa;
    __syncthreads();

    float h = bm1[j];
    for (int i = 0; i < HID; i++) h += Wm1[j * HID + i] * s_xa[i];
    h = h / (1.f + expf(-h));         // silu
    s_h[j] = h;
    __syncthreads();

    float xm = xa + bm2[j];
    for (int i = 0; i < HID; i++) xm += Wm2[j * HID + i] * s_h[i];
    s_xm[j] = xm;
    __syncthreads();

    if (j < E_) {
        float l = bc[j];
        for (int i = 0; i < HID; i++) l += Wc[j * HID + i] * s_xm[i];
        s_l[j] = l;
    }
    __syncthreads();
    if (j == 0) {
        float mx = s_l[0];
        for (int e = 1; e < E_; e++) mx = fmaxf(mx, s_l[e]);
        float sm = 0.f, ex[E_];
        for (int e = 0; e < E_; e++) { ex[e] = expf(s_l[e] - mx); sm += ex[e]; }
        float inv = 1.f / sm;
        for (int e = 0; e < E_; e++) g_rw[b * E_ + e] = ex[e] * inv;
    }
}

// ---------------- kernel 3: mix expert weights -> g_weff [b][tap][cout][cin] fp16 ----------------
// grid=COUT, 256 threads = (cin-pair 0..127, batch-half 0..1). Single 36 KB
// weight read per block; half2 coalesced stores; 16-batch serial depth.
__global__ __launch_bounds__(256) void mix_kernel(const float* __restrict__ weight) {
    const int o = blockIdx.x, tid = threadIdx.x;
    const int t2 = tid & 127;            // cin pair
    const int bh = tid >> 7;             // batch half
    __shared__ float ws[E_ * CIN * TAPS];   // 36 KB: weight[:, o, :, :]
    __shared__ float srw[B_ * E_];
    for (int e = 0; e < E_; e++) {
        const float* src = weight + (size_t)(e * COUT + o) * (CIN * TAPS);
        for (int i = tid; i < CIN * TAPS; i += 256) ws[e * CIN * TAPS + i] = src[i];
    }
    for (int i = tid; i < B_ * E_; i += 256) srw[i] = g_rw[i];
    __syncthreads();

    const int c0 = t2 * 2;
    float wv[E_][TAPS][2];
    #pragma unroll
    for (int e = 0; e < E_; e++)
        #pragma unroll
        for (int t = 0; t < TAPS; t++) {
            wv[e][t][0] = ws[e * CIN * TAPS + c0 * TAPS + t];
            wv[e][t][1] = ws[e * CIN * TAPS + (c0 + 1) * TAPS + t];
        }

    #pragma unroll 1
    for (int bi = 0; bi < 16; bi++) {
        const int b = bh * 16 + bi;
        float r0 = srw[b * 4 + 0], r1 = srw[b * 4 + 1];
        float r2 = srw[b * 4 + 2], r3 = srw[b * 4 + 3];
        #pragma unroll
        for (int t = 0; t < TAPS; t++) {
            float v0 = r0 * wv[0][t][0] + r1 * wv[1][t][0] + r2 * wv[2][t][0] + r3 * wv[3][t][0];
            float v1 = r0 * wv[0][t][1] + r1 * wv[1][t][1] + r2 * wv[2][t][1] + r3 * wv[3][t][1];
            __half2 hv = __floats2half2_rn(v0, v1);
            *reinterpret_cast<__half2*>(
                g_weff + (((size_t)b * TAPS + t) * COUT + o) * CIN + c0) = hv;
        }
    }
}

// ---------------- kernel 4: batched implicit-GEMM conv via mma.sync (HMMA) ----------------
// (R12 best: 4 warps 64x64, triple-buffered A, async double-buffered sX)
// Only delta vs R12: epilogue uses st.global.cs (streaming) stores.
constexpr int PIXB = 144;                 // bytes per pixel in sX (64 cin + 8 pad halves)
constexpr int ROWB = 34 * PIXB;           // 4896 B per image row (halo cols 0 and 33)
constexpr int SXB  = 6 * ROWB;            // 29376 per sX buffer
constexpr int SA_OFF = 59392;             // >= 2*SXB, 1024-aligned
constexpr int SA_BYTES = 128 * 128;       // 16 KB per A buffer
constexpr int CONV_SMEM = SA_OFF + 3 * SA_BYTES;   // 108544

__global__ __launch_bounds__(128, 2) void conv_kernel(float* __restrict__ out) {
    extern __shared__ char smem[];
    char* sx = smem;
    const uint32_t sxa = smem_u32(sx);
    const uint32_t saa[3] = { sxa + SA_OFF, sxa + SA_OFF + SA_BYTES,
                              sxa + SA_OFF + 2 * SA_BYTES };

    const int tid = threadIdx.x, lid = tid & 31, wid = tid >> 5;
    const int nt = blockIdx.x, mt = blockIdx.y, b = blockIdx.z;
    const int wm = wid & 1, wn = wid >> 1;
    const int h0 = nt * 4;

    const __half* __restrict__ xb2 = g_xh + (size_t)b * HW * CIN;   // pixel-major
    const __half* __restrict__ wbase =
        g_weff + ((size_t)b * TAPS * COUT + (size_t)mt * 128) * CIN;

    float acc[4][8][4];
    #pragma unroll
    for (int mi = 0; mi < 4; mi++)
        #pragma unroll
        for (int ni = 0; ni < 8; ni++)
            #pragma unroll
            for (int q = 0; q < 4; q++) acc[mi][ni][q] = 0.f;

    uint32_t bg[4];
    {
        int kh = (lid >> 3) & 1, nodd = lid >> 4, pr = lid & 7;
        #pragma unroll
        for (int g = 0; g < 4; g++) {
            int n = wn * 64 + (2 * g + nodd) * 8 + pr;
            int r = n >> 5, w = n & 31;
            bg[g] = sxa + (uint32_t)(((r + 1) * 34 + (w + 1)) * PIXB + kh * 16);
        }
    }

    auto prefetchA = [&](int tap, int cc, uint32_t dst) {
        const __half* asrc = wbase + (size_t)tap * COUT * CIN + cc * 64;
        #pragma unroll
        for (int i = 0; i < 8; i++) {
            int idx = i * 128 + tid;
            int m = idx >> 3, j = idx & 7;
            cp_async16(dst + SW128((uint32_t)(m * 128 + j * 16)), asrc + m * CIN + j * 8);
        }
    };

    auto fillXasync = [&](int cn) {
        const int w = tid >> 2, jj = tid & 3;
        const uint32_t dstb = sxa + (uint32_t)((cn & 1) * SXB + (1 + w) * PIXB + jj * 32);
        const char* srcb = (const char*)(xb2 + (size_t)cn * 64) + (size_t)w * (CIN * 2) + jj * 32;
        #pragma unroll
        for (int rr = 0; rr < 6; rr++) {
            int h = h0 + rr - 1;
            if ((unsigned)h < 32u) {
                const char* s = srcb + (size_t)h * (32 * CIN * 2);
                uint32_t d = dstb + rr * ROWB;
                cp_async16(d, s);
                cp_async16(d + 16, s + 16);
            }
        }
    };

    for (int i = tid; i < 216; i += 128) {       // halo cols: 2 buf x 6 rr x 2 col x 9 u4
        int u = i % 9, rem = i / 9;
        int col = rem & 1, rr = (rem >> 1) % 6, bf = rem / 12;
        *reinterpret_cast<uint4*>(sx + bf * SXB + rr * ROWB + (col ? 33 : 0) * PIXB + u * 16) =
            make_uint4(0u, 0u, 0u, 0u);
    }
    if (nt == 0 || nt == 7) {                    // one out-of-range image row per CTA
        int RR = (nt == 0) ? 0 : 5;
        for (int i = tid; i < 612; i += 128) {   // 2 buf x 306 u4
            int bf = i / 306, u = i % 306;
            *reinterpret_cast<uint4*>(sx + bf * SXB + RR * ROWB + u * 16) =
                make_uint4(0u, 0u, 0u, 0u);
        }
    }
    fillXasync(0);
    prefetchA(0, 0, saa[0]);
    CP_COMMIT();                                  // group: sX(0) + A(0)
    prefetchA(1, 0, saa[1]);
    CP_COMMIT();                                  // group: A(1)

    #pragma unroll 1
    for (int cc = 0; cc < 4; cc++) {
        const uint32_t xoff = (uint32_t)((cc & 1) * SXB);
        #pragma unroll
        for (int tap = 0; tap < TAPS; tap++) {
            const bool lastS = (cc == 3) && (tap == 8);
            if (lastS) { CP_WAIT(0); } else { CP_WAIT(1); }   // A(s) [+sX(cc)] resident
            __syncthreads();

            if (!((cc == 3) && (tap >= 7))) {
                const int ntap = (tap + 2 < TAPS) ? tap + 2 : tap + 2 - TAPS;
                const int ncc  = (tap + 2 < TAPS) ? cc : cc + 1;
                prefetchA(ntap, ncc, saa[(tap + 2) % 3]);
                if (tap == 0 && cc < 3) fillXasync(cc + 1);    // next chunk's sX, async
                CP_COMMIT();
            }

            const uint32_t sa = saa[tap % 3];
            const int dh = tap / 3 - 1, dw = tap % 3 - 1;
            const int delta = (dh * 34 + dw) * PIXB;

            #pragma unroll
            for (int ks = 0; ks < 4; ks++) {
                uint32_t afr[4][4];
                #pragma unroll
                for (int mi = 0; mi < 4; mi++) {
                    int row = wm * 64 + mi * 16 + (lid & 15);
                    uint32_t off = (uint32_t)(row * 128 + ks * 32 + (lid >> 4) * 16);
                    ldsm_x4(afr[mi], sa + SW128(off));
                }
                uint32_t breg[4][4];
                const uint32_t dlt = xoff + (uint32_t)(delta + ks * 32);
                #pragma unroll
                for (int g = 0; g < 4; g++) ldsm_x4(breg[g], bg[g] + dlt);
                #pragma unroll
                for (int mi = 0; mi < 4; mi++)
                    #pragma unroll
                    for (int nb = 0; nb < 8; nb++) {
                        uint32_t b0 = breg[nb >> 1][(nb & 1) * 2];
                        uint32_t b1 = breg[nb >> 1][(nb & 1) * 2 + 1];
                        mma16816(acc[mi][nb], afr[mi], b0, b1);
                    }
            }
        }
    }

    // ---- epilogue: accum regs -> out (streaming stores) ----
    #pragma unroll
    for (int mi = 0; mi < 4; mi++) {
        #pragma unroll
        for (int ni = 0; ni < 8; ni++) {
            int row = mt * 128 + wm * 64 + mi * 16 + (lid >> 2);
            int col = nt * 128 + wn * 64 + ni * 8 + (lid & 3) * 2;
            float* op0 = out + ((size_t)b * COUT + row) * HW + col;
            float* op1 = op0 + 8 * HW;   // row + 8
            stg_cs_f2(op0, acc[mi][ni][0], acc[mi][ni][1]);
            stg_cs_f2(op1, acc[mi][ni][2], acc[mi][ni][3]);
        }
    }
}

// ---------------- launcher ----------------
extern "C" void kernel_launch(void* const* d_in, const int* in_sizes, int n_in,
                              void* d_out, int out_size) {
    const float* x      = (const float*)d_in[0];
    const float* te     = (const float*)d_in[1];
    const float* weight = (const float*)d_in[2];
    const float* Wq = (const float*)d_in[3],  *bq = (const float*)d_in[4];
    const float* Wk = (const float*)d_in[5],  *bk = (const float*)d_in[6];
    const float* Wv = (const float*)d_in[7],  *bv = (const float*)d_in[8];
    const float* Wm1 = (const float*)d_in[9],  *bm1 = (const float*)d_in[10];
    const float* Wm2 = (const float*)d_in[11], *bm2 = (const float*)d_in[12];
    const float* Wc  = (const float*)d_in[13], *bc  = (const float*)d_in[14];
    float* out = (float*)d_out;

    cudaFuncSetAttribute(conv_kernel, cudaFuncAttributeMaxDynamicSharedMemorySize,
                         CONV_SMEM);

    pool_convert_kernel<<<dim3(32, B_), 256>>>(x);
    router_kernel<<<B_, HID>>>(te, Wq, bq, Wk, bk, Wv, bv, Wm1, bm1, Wm2, bm2, Wc, bc);
    mix_kernel<<<COUT, 256>>>(weight);
    conv_kernel<<<dim3(8, 2, B_), 128, CONV_SMEM>>>(out);
}